// round 4
// baseline (speedup 1.0000x reference)
#include <cuda_runtime.h>

#define NUM_G 4096
#define D4    32          // 128 floats = 32 float4 per row
#define TPB   512
#define RG    16          // row groups in pass 1 (TPB / 32)
#define EPSV  1e-5f

__device__ int g_seg_off[NUM_G + 1];

// Scan-based offsets: thread i compares batch[i-1] vs batch[i] (sorted) and
// fills g_seg_off[g] = lower_bound(g) for every boundary it owns.
// Runtime dtype detection: if batch is int64 (LE), odd 32-bit words near the end
// are high words of values < 4096 -> all zero. If int32, tail values ~4095.
__global__ void offsets_kernel(const int* __restrict__ b32, int n)
{
    int i = blockIdx.x * blockDim.x + threadIdx.x;
    if (i > n) return;
    int probe = b32[n - 1] | b32[n - 3] | b32[n - 5] | b32[n - 7];
    int sh = (probe == 0) ? 1 : 0;   // 1 => int64, read low words at stride 2
    int prev = (i > 0) ? b32[(long long)(i - 1) << sh] : -1;
    int cur  = (i < n) ? b32[(long long)i << sh]       : NUM_G;
    for (int g = prev + 1; g <= cur; ++g)
        g_seg_off[g] = i;
}

__device__ __forceinline__ void acc(float4& s, float4& q, const float4 v)
{
    s.x += v.x; s.y += v.y; s.z += v.z; s.w += v.w;
    q.x += v.x * v.x; q.y += v.y * v.y;
    q.z += v.z * v.z; q.w += v.w * v.w;
}

__global__ __launch_bounds__(TPB, 3) void graphnorm_kernel(
    const float4* __restrict__ x4,
    const float*  __restrict__ weight,
    const float*  __restrict__ bias,
    float4*       __restrict__ out4)
{
    __shared__ float4 red_s[RG][D4];
    __shared__ float4 red_q[RG][D4];
    __shared__ float4 sc_s[D4];
    __shared__ float4 sh_s[D4];

    const int g   = blockIdx.x;
    const int tid = threadIdx.x;
    const int c4  = tid & (D4 - 1);   // float4 column
    const int rg  = tid >> 5;         // row group 0..RG-1

    const int start = g_seg_off[g];
    const int end   = g_seg_off[g + 1];
    const int cnt   = end - start;

    // ---- Pass 1: per-column sum / sumsq (unroll x2) ----
    float4 s = make_float4(0.f, 0.f, 0.f, 0.f);
    float4 q = make_float4(0.f, 0.f, 0.f, 0.f);
    int r = start + rg;
    for (; r + RG < end; r += 2 * RG) {
        float4 v0 = x4[r * D4 + c4];
        float4 v1 = x4[(r + RG) * D4 + c4];
        acc(s, q, v0);
        acc(s, q, v1);
    }
    if (r < end) {
        float4 v = x4[r * D4 + c4];
        acc(s, q, v);
    }
    red_s[rg][c4] = s;
    red_q[rg][c4] = q;
    __syncthreads();

    // ---- Flat reduction + fold into scale/shift (warp 0 only) ----
    if (rg == 0) {
        float4 S = red_s[0][c4];
        float4 Q = red_q[0][c4];
        #pragma unroll
        for (int k = 1; k < RG; ++k) {
            float4 a = red_s[k][c4];
            S.x += a.x; S.y += a.y; S.z += a.z; S.w += a.w;
            float4 b = red_q[k][c4];
            Q.x += b.x; Q.y += b.y; Q.z += b.z; Q.w += b.w;
        }
        float4 w = reinterpret_cast<const float4*>(weight)[c4];
        float4 b = reinterpret_cast<const float4*>(bias)[c4];
        float4 sc, sh;
        if (cnt > 1) {
            float inv_n = 1.0f / (float)cnt;
            float mx = S.x * inv_n, my = S.y * inv_n, mz = S.z * inv_n, mw = S.w * inv_n;
            float vx = Q.x * inv_n - mx * mx;
            float vy = Q.y * inv_n - my * my;
            float vz = Q.z * inv_n - mz * mz;
            float vw = Q.w * inv_n - mw * mw;
            sc.x = w.x * rsqrtf(vx + EPSV);
            sc.y = w.y * rsqrtf(vy + EPSV);
            sc.z = w.z * rsqrtf(vz + EPSV);
            sc.w = w.w * rsqrtf(vw + EPSV);
            sh.x = b.x - mx * sc.x;
            sh.y = b.y - my * sc.y;
            sh.z = b.z - mz * sc.z;
            sh.w = b.w - mw * sc.w;
        } else {
            // cnt <= 1: reference leaves mean=0, var=1
            float rr = rsqrtf(1.0f + EPSV);
            sc.x = w.x * rr; sc.y = w.y * rr; sc.z = w.z * rr; sc.w = w.w * rr;
            sh = b;
        }
        sc_s[c4] = sc;
        sh_s[c4] = sh;
    }
    __syncthreads();

    // ---- Pass 2: normalize (unroll x2, hoisted sc/sh). x re-read hits L2;
    //      streaming stores keep the output from evicting x segments. ----
    const float4 sc = sc_s[c4];
    const float4 sh = sh_s[c4];
    const int jend = end * D4;
    int j = start * D4 + tid;
    for (; j + TPB < jend; j += 2 * TPB) {
        float4 v0 = x4[j];
        float4 v1 = x4[j + TPB];
        float4 o0, o1;
        o0.x = v0.x * sc.x + sh.x; o0.y = v0.y * sc.y + sh.y;
        o0.z = v0.z * sc.z + sh.z; o0.w = v0.w * sc.w + sh.w;
        o1.x = v1.x * sc.x + sh.x; o1.y = v1.y * sc.y + sh.y;
        o1.z = v1.z * sc.z + sh.z; o1.w = v1.w * sc.w + sh.w;
        __stcs(&out4[j      ], o0);
        __stcs(&out4[j + TPB], o1);
    }
    if (j < jend) {
        float4 v = x4[j];
        float4 o;
        o.x = v.x * sc.x + sh.x;
        o.y = v.y * sc.y + sh.y;
        o.z = v.z * sc.z + sh.z;
        o.w = v.w * sc.w + sh.w;
        __stcs(&out4[j], o);
    }
}

extern "C" void kernel_launch(void* const* d_in, const int* in_sizes, int n_in,
                              void* d_out, int out_size)
{
    const float* x      = (const float*)d_in[0];
    const int*   batch  = (const int*)d_in[1];   // int32 or int64; detected on device
    const float* weight = (const float*)d_in[2];
    const float* bias   = (const float*)d_in[3];
    float*       out    = (float*)d_out;

    int n = in_sizes[1];  // number of nodes

    offsets_kernel<<<(n + 1 + 255) / 256, 256>>>(batch, n);
    graphnorm_kernel<<<NUM_G, TPB>>>(
        reinterpret_cast<const float4*>(x), weight, bias,
        reinterpret_cast<float4*>(out));
}

// round 6
// speedup vs baseline: 1.1396x; 1.1396x over previous
#include <cuda_runtime.h>

#define NUM_G 4096
#define D4    32          // 128 floats = 32 float4 per row
#define TPB   512
#define RG    16          // row groups in pass 1 (TPB / 32)
#define EPSV  1e-5f

__device__ int g_seg_off[NUM_G + 1];

// Scan-based offsets: thread i compares batch[i-1] vs batch[i] (sorted) and
// fills g_seg_off[g] = lower_bound(g) for every boundary it owns.
// Runtime dtype detection: if batch is int64 (LE), odd 32-bit words near the end
// are high words of values < 4096 -> all zero. If int32, tail values ~4095.
__global__ void offsets_kernel(const int* __restrict__ b32, int n)
{
    int i = blockIdx.x * blockDim.x + threadIdx.x;
    if (i > n) return;
    int probe = b32[n - 1] | b32[n - 3] | b32[n - 5] | b32[n - 7];
    int sh = (probe == 0) ? 1 : 0;   // 1 => int64, read low words at stride 2
    int prev = (i > 0) ? b32[(long long)(i - 1) << sh] : -1;
    int cur  = (i < n) ? b32[(long long)i << sh]       : NUM_G;
    for (int g = prev + 1; g <= cur; ++g)
        g_seg_off[g] = i;
}

__global__ __launch_bounds__(TPB) void graphnorm_kernel(
    const float4* __restrict__ x4,
    const float*  __restrict__ weight,
    const float*  __restrict__ bias,
    float4*       __restrict__ out4)
{
    __shared__ float4 red_s[RG][D4];
    __shared__ float4 red_q[RG][D4];
    __shared__ float4 sc_s[D4];
    __shared__ float4 sh_s[D4];

    const int g   = blockIdx.x;
    const int tid = threadIdx.x;
    const int c4  = tid & (D4 - 1);   // float4 column
    const int rg  = tid >> 5;         // row group 0..15

    const int start = g_seg_off[g];
    const int end   = g_seg_off[g + 1];
    const int cnt   = end - start;

    // ---- Pass 1: per-column sum / sumsq (unroll x2 for MLP) ----
    float4 s = make_float4(0.f, 0.f, 0.f, 0.f);
    float4 q = make_float4(0.f, 0.f, 0.f, 0.f);
    int r = start + rg;
    for (; r + RG < end; r += 2 * RG) {
        float4 v0 = x4[r * D4 + c4];
        float4 v1 = x4[(r + RG) * D4 + c4];
        s.x += v0.x; s.y += v0.y; s.z += v0.z; s.w += v0.w;
        q.x += v0.x * v0.x; q.y += v0.y * v0.y;
        q.z += v0.z * v0.z; q.w += v0.w * v0.w;
        s.x += v1.x; s.y += v1.y; s.z += v1.z; s.w += v1.w;
        q.x += v1.x * v1.x; q.y += v1.y * v1.y;
        q.z += v1.z * v1.z; q.w += v1.w * v1.w;
    }
    if (r < end) {
        float4 v = x4[r * D4 + c4];
        s.x += v.x; s.y += v.y; s.z += v.z; s.w += v.w;
        q.x += v.x * v.x; q.y += v.y * v.y;
        q.z += v.z * v.z; q.w += v.w * v.w;
    }
    red_s[rg][c4] = s;
    red_q[rg][c4] = q;
    __syncthreads();

    #pragma unroll
    for (int h = RG / 2; h >= 1; h >>= 1) {
        if (rg < h) {
            float4 a = red_s[rg][c4], b = red_s[rg + h][c4];
            a.x += b.x; a.y += b.y; a.z += b.z; a.w += b.w;
            red_s[rg][c4] = a;
            float4 c = red_q[rg][c4], d = red_q[rg + h][c4];
            c.x += d.x; c.y += d.y; c.z += d.z; c.w += d.w;
            red_q[rg][c4] = c;
        }
        __syncthreads();
    }

    // ---- Fold into scale/shift (warp 0) ----
    if (rg == 0) {
        float4 w = reinterpret_cast<const float4*>(weight)[c4];
        float4 b = reinterpret_cast<const float4*>(bias)[c4];
        float4 sc, sh;
        if (cnt > 1) {
            float4 S = red_s[0][c4];
            float4 Q = red_q[0][c4];
            float inv_n = 1.0f / (float)cnt;
            float mx = S.x * inv_n, my = S.y * inv_n, mz = S.z * inv_n, mw = S.w * inv_n;
            float vx = Q.x * inv_n - mx * mx;
            float vy = Q.y * inv_n - my * my;
            float vz = Q.z * inv_n - mz * mz;
            float vw = Q.w * inv_n - mw * mw;
            sc.x = w.x * rsqrtf(vx + EPSV);
            sc.y = w.y * rsqrtf(vy + EPSV);
            sc.z = w.z * rsqrtf(vz + EPSV);
            sc.w = w.w * rsqrtf(vw + EPSV);
            sh.x = b.x - mx * sc.x;
            sh.y = b.y - my * sc.y;
            sh.z = b.z - mz * sc.z;
            sh.w = b.w - mw * sc.w;
        } else {
            // cnt <= 1: reference leaves mean=0, var=1
            float rr = rsqrtf(1.0f + EPSV);
            sc.x = w.x * rr; sc.y = w.y * rr; sc.z = w.z * rr; sc.w = w.w * rr;
            sh = b;
        }
        sc_s[c4] = sc;
        sh_s[c4] = sh;
    }
    __syncthreads();

    // ---- Pass 2: normalize. x re-read hits L2; output uses streaming
    //      stores (evict-first) so it doesn't evict x segments from L2. ----
    const int jend = end * D4;
    for (int j = start * D4 + tid; j < jend; j += TPB) {
        int c = j & (D4 - 1);
        float4 v  = x4[j];
        float4 sc = sc_s[c];
        float4 sh = sh_s[c];
        float4 o;
        o.x = v.x * sc.x + sh.x;
        o.y = v.y * sc.y + sh.y;
        o.z = v.z * sc.z + sh.z;
        o.w = v.w * sc.w + sh.w;
        __stcs(&out4[j], o);
    }
}

extern "C" void kernel_launch(void* const* d_in, const int* in_sizes, int n_in,
                              void* d_out, int out_size)
{
    const float* x      = (const float*)d_in[0];
    const int*   batch  = (const int*)d_in[1];   // int32 or int64; detected on device
    const float* weight = (const float*)d_in[2];
    const float* bias   = (const float*)d_in[3];
    float*       out    = (float*)d_out;

    int n = in_sizes[1];  // number of nodes

    offsets_kernel<<<(n + 1 + 255) / 256, 256>>>(batch, n);
    graphnorm_kernel<<<NUM_G, TPB>>>(
        reinterpret_cast<const float4*>(x), weight, bias,
        reinterpret_cast<float4*>(out));
}

// round 7
// speedup vs baseline: 1.2208x; 1.0713x over previous
#include <cuda_runtime.h>

#define NUM_G 4096
#define D4    32          // 128 floats = 32 float4 per row
#define DHID  128
#define TPB   512
#define RG    16          // row groups in pass 1 (TPB / 32)
#define EPSV  1e-5f

__device__ int g_seg_off[NUM_G + 1];

// Scan-based offsets: thread i compares batch[i-1] vs batch[i] (sorted) and
// fills g_seg_off[g] = lower_bound(g) for every boundary it owns.
// Runtime dtype detection: if batch is int64 (LE), odd 32-bit words near the end
// are high words of values < 4096 -> all zero. If int32, tail values ~4095.
__global__ void offsets_kernel(const int* __restrict__ b32, int n)
{
    int i = blockIdx.x * blockDim.x + threadIdx.x;
    if (i > n) return;
    int probe = b32[n - 1] | b32[n - 3] | b32[n - 5] | b32[n - 7];
    int sh = (probe == 0) ? 1 : 0;   // 1 => int64, read low words at stride 2
    int prev = (i > 0) ? b32[(long long)(i - 1) << sh] : -1;
    int cur  = (i < n) ? b32[(long long)i << sh]       : NUM_G;
    for (int g = prev + 1; g <= cur; ++g)
        g_seg_off[g] = i;
}

__global__ __launch_bounds__(TPB) void graphnorm_kernel(
    const float4* __restrict__ x4,
    const float*  __restrict__ weight,
    const float*  __restrict__ bias,
    float4*       __restrict__ out4)
{
    __shared__ float4 red_s[RG][D4];
    __shared__ float4 red_q[RG][D4];
    __shared__ float4 sc_s[D4];
    __shared__ float4 sh_s[D4];

    const int g   = blockIdx.x;
    const int tid = threadIdx.x;
    const int c4  = tid & (D4 - 1);   // float4 column
    const int rg  = tid >> 5;         // row group 0..15

    const int start = g_seg_off[g];
    const int end   = g_seg_off[g + 1];
    const int cnt   = end - start;

    // ---- Pass 1: per-column sum / sumsq (unroll x2 for MLP) ----
    float4 s = make_float4(0.f, 0.f, 0.f, 0.f);
    float4 q = make_float4(0.f, 0.f, 0.f, 0.f);
    int r = start + rg;
    for (; r + RG < end; r += 2 * RG) {
        float4 v0 = x4[r * D4 + c4];
        float4 v1 = x4[(r + RG) * D4 + c4];
        s.x += v0.x; s.y += v0.y; s.z += v0.z; s.w += v0.w;
        q.x += v0.x * v0.x; q.y += v0.y * v0.y;
        q.z += v0.z * v0.z; q.w += v0.w * v0.w;
        s.x += v1.x; s.y += v1.y; s.z += v1.z; s.w += v1.w;
        q.x += v1.x * v1.x; q.y += v1.y * v1.y;
        q.z += v1.z * v1.z; q.w += v1.w * v1.w;
    }
    if (r < end) {
        float4 v = x4[r * D4 + c4];
        s.x += v.x; s.y += v.y; s.z += v.z; s.w += v.w;
        q.x += v.x * v.x; q.y += v.y * v.y;
        q.z += v.z * v.z; q.w += v.w * v.w;
    }
    red_s[rg][c4] = s;
    red_q[rg][c4] = q;
    __syncthreads();

    // ---- Flat parallel reduction + fold into scale/shift.
    //      128 threads (4 warps), one scalar column each: 16 conflict-free
    //      LDS per sum, fully pipelined. 2 barriers total instead of 6. ----
    if (tid < DHID) {
        const float* ps = reinterpret_cast<const float*>(red_s);
        const float* pq = reinterpret_cast<const float*>(red_q);
        float S = 0.f, Q = 0.f;
        #pragma unroll
        for (int k = 0; k < RG; ++k) {
            S += ps[k * DHID + tid];
            Q += pq[k * DHID + tid];
        }
        float w = weight[tid];
        float b = bias[tid];
        float sc, sh;
        if (cnt > 1) {
            float inv_n = 1.0f / (float)cnt;
            float m = S * inv_n;
            float v = Q * inv_n - m * m;
            sc = w * rsqrtf(v + EPSV);
            sh = b - m * sc;
        } else {
            // cnt <= 1: reference leaves mean=0, var=1
            sc = w * rsqrtf(1.0f + EPSV);
            sh = b;
        }
        reinterpret_cast<float*>(sc_s)[tid] = sc;
        reinterpret_cast<float*>(sh_s)[tid] = sh;
    }
    __syncthreads();

    // ---- Pass 2: normalize. x re-read hits L2; output uses streaming
    //      stores (evict-first) so it doesn't evict x segments from L2. ----
    const int jend = end * D4;
    for (int j = start * D4 + tid; j < jend; j += TPB) {
        int c = j & (D4 - 1);
        float4 v  = x4[j];
        float4 sc = sc_s[c];
        float4 sh = sh_s[c];
        float4 o;
        o.x = v.x * sc.x + sh.x;
        o.y = v.y * sc.y + sh.y;
        o.z = v.z * sc.z + sh.z;
        o.w = v.w * sc.w + sh.w;
        __stcs(&out4[j], o);
    }
}

extern "C" void kernel_launch(void* const* d_in, const int* in_sizes, int n_in,
                              void* d_out, int out_size)
{
    const float* x      = (const float*)d_in[0];
    const int*   batch  = (const int*)d_in[1];   // int32 or int64; detected on device
    const float* weight = (const float*)d_in[2];
    const float* bias   = (const float*)d_in[3];
    float*       out    = (float*)d_out;

    int n = in_sizes[1];  // number of nodes

    offsets_kernel<<<(n + 1 + 255) / 256, 256>>>(batch, n);
    graphnorm_kernel<<<NUM_G, TPB>>>(
        reinterpret_cast<const float4*>(x), weight, bias,
        reinterpret_cast<float4*>(out));
}

// round 8
// speedup vs baseline: 1.2474x; 1.0218x over previous
#include <cuda_runtime.h>

#define NUM_G 4096
#define D4    32          // 128 floats = 32 float4 per row
#define DHID  128
#define TPB   512
#define RG    16          // row groups in pass 1 (TPB / 32)
#define EPSV  1e-5f

__device__ int g_seg_off[NUM_G + 1];

// Scan-based offsets: thread i compares batch[i-1] vs batch[i] (sorted) and
// fills g_seg_off[g] = lower_bound(g) for every boundary it owns.
// Runtime dtype detection: if batch is int64 (LE), odd 32-bit words near the end
// are high words of values < 4096 -> all zero. If int32, tail values ~4095.
__global__ void offsets_kernel(const int* __restrict__ b32, int n)
{
    int i = blockIdx.x * blockDim.x + threadIdx.x;
    if (i > n) return;
    int probe = b32[n - 1] | b32[n - 3] | b32[n - 5] | b32[n - 7];
    int sh = (probe == 0) ? 1 : 0;   // 1 => int64, read low words at stride 2
    int prev = (i > 0) ? b32[(long long)(i - 1) << sh] : -1;
    int cur  = (i < n) ? b32[(long long)i << sh]       : NUM_G;
    for (int g = prev + 1; g <= cur; ++g)
        g_seg_off[g] = i;
}

__device__ __forceinline__ void acc(float4& s, float4& q, const float4 v)
{
    s.x += v.x; s.y += v.y; s.z += v.z; s.w += v.w;
    q.x += v.x * v.x; q.y += v.y * v.y;
    q.z += v.z * v.z; q.w += v.w * v.w;
}

__global__ __launch_bounds__(TPB, 2) void graphnorm_kernel(
    const float4* __restrict__ x4,
    const float*  __restrict__ weight,
    const float*  __restrict__ bias,
    float4*       __restrict__ out4)
{
    __shared__ float4 red_s[RG][D4];
    __shared__ float4 red_q[RG][D4];
    __shared__ float4 sc_s[D4];
    __shared__ float4 sh_s[D4];

    const int g   = blockIdx.x;
    const int tid = threadIdx.x;
    const int c4  = tid & (D4 - 1);   // float4 column
    const int rg  = tid >> 5;         // row group 0..15

    const int start = g_seg_off[g];
    const int end   = g_seg_off[g + 1];
    const int cnt   = end - start;

    // ---- Pass 1: per-column sum / sumsq (unroll x4: 4 independent
    //      LDG.128 per warp in flight -> 32 KB/block MLP) ----
    float4 s = make_float4(0.f, 0.f, 0.f, 0.f);
    float4 q = make_float4(0.f, 0.f, 0.f, 0.f);
    int r = start + rg;
    for (; r + 3 * RG < end; r += 4 * RG) {
        float4 v0 = x4[(r         ) * D4 + c4];
        float4 v1 = x4[(r +     RG) * D4 + c4];
        float4 v2 = x4[(r + 2 * RG) * D4 + c4];
        float4 v3 = x4[(r + 3 * RG) * D4 + c4];
        acc(s, q, v0);
        acc(s, q, v1);
        acc(s, q, v2);
        acc(s, q, v3);
    }
    for (; r < end; r += RG) {
        float4 v = x4[r * D4 + c4];
        acc(s, q, v);
    }
    red_s[rg][c4] = s;
    red_q[rg][c4] = q;
    __syncthreads();

    // ---- Flat parallel reduction + fold into scale/shift.
    //      128 threads, one scalar column each: 16 conflict-free LDS per
    //      sum, fully pipelined. 2 barriers total. ----
    if (tid < DHID) {
        const float* ps = reinterpret_cast<const float*>(red_s);
        const float* pq = reinterpret_cast<const float*>(red_q);
        float S = 0.f, Q = 0.f;
        #pragma unroll
        for (int k = 0; k < RG; ++k) {
            S += ps[k * DHID + tid];
            Q += pq[k * DHID + tid];
        }
        float w = weight[tid];
        float b = bias[tid];
        float sc, sh;
        if (cnt > 1) {
            float inv_n = 1.0f / (float)cnt;
            float m = S * inv_n;
            float v = Q * inv_n - m * m;
            sc = w * rsqrtf(v + EPSV);
            sh = b - m * sc;
        } else {
            // cnt <= 1: reference leaves mean=0, var=1
            sc = w * rsqrtf(1.0f + EPSV);
            sh = b;
        }
        reinterpret_cast<float*>(sc_s)[tid] = sc;
        reinterpret_cast<float*>(sh_s)[tid] = sh;
    }
    __syncthreads();

    // ---- Pass 2: normalize (unroll x2, hoisted sc/sh: j & 31 == tid & 31
    //      is loop-invariant). x re-read hits L2; streaming stores keep the
    //      output from evicting x segments. ----
    const float4 sc = sc_s[c4];
    const float4 sh = sh_s[c4];
    const int jend = end * D4;
    int j = start * D4 + tid;
    for (; j + TPB < jend; j += 2 * TPB) {
        float4 v0 = x4[j];
        float4 v1 = x4[j + TPB];
        float4 o0, o1;
        o0.x = v0.x * sc.x + sh.x; o0.y = v0.y * sc.y + sh.y;
        o0.z = v0.z * sc.z + sh.z; o0.w = v0.w * sc.w + sh.w;
        o1.x = v1.x * sc.x + sh.x; o1.y = v1.y * sc.y + sh.y;
        o1.z = v1.z * sc.z + sh.z; o1.w = v1.w * sc.w + sh.w;
        __stcs(&out4[j      ], o0);
        __stcs(&out4[j + TPB], o1);
    }
    if (j < jend) {
        float4 v = x4[j];
        float4 o;
        o.x = v.x * sc.x + sh.x;
        o.y = v.y * sc.y + sh.y;
        o.z = v.z * sc.z + sh.z;
        o.w = v.w * sc.w + sh.w;
        __stcs(&out4[j], o);
    }
}

extern "C" void kernel_launch(void* const* d_in, const int* in_sizes, int n_in,
                              void* d_out, int out_size)
{
    const float* x      = (const float*)d_in[0];
    const int*   batch  = (const int*)d_in[1];   // int32 or int64; detected on device
    const float* weight = (const float*)d_in[2];
    const float* bias   = (const float*)d_in[3];
    float*       out    = (float*)d_out;

    int n = in_sizes[1];  // number of nodes

    offsets_kernel<<<(n + 1 + 255) / 256, 256>>>(batch, n);
    graphnorm_kernel<<<NUM_G, TPB>>>(
        reinterpret_cast<const float4*>(x), weight, bias,
        reinterpret_cast<float4*>(out));
}